// round 2
// baseline (speedup 1.0000x reference)
#include <cuda_runtime.h>
#include <math.h>

#define B_ 4
#define L_ 4096
#define D_ 2048
#define M_ (B_*L_)            // 16384 rows total
#define LCHUNK 128
#define NCHUNK (L_/LCHUNK)    // 32

// ---------------- scratch (device globals; no allocation allowed) ----------
__device__ float g_gate[33554432];   // [M_, D_] a_t = sigmoid(f)
__device__ float g_bin [33554432];   // [M_, D_] b_t = silu(i)*(1-gate); becomes o after scan
__device__ float g_g   [33554432];   // [M_, D_] g projection; becomes gated out after rms_gate
__device__ float g_cA  [B_*NCHUNK*D_];
__device__ float g_cH  [B_*NCHUNK*D_];
__device__ float g_pre [B_*NCHUNK*D_];

__device__ __forceinline__ float fsigmoid(float x) {
    return 1.0f / (1.0f + __expf(-x));
}

// ---------------------------------------------------------------------------
// Kernel 1: fused triple projection GEMM.
// i/f/g[m,n] = sum_k X[m,k] * W{i,f,g}[n,k]   (nn.Linear: y = x @ W^T)
// Tile: BM=128, BN=64, BK=16; 256 threads; micro-tile 8x4; 3 accumulator sets.
// Epilogue fuses gate = sigmoid(f), b = silu(i)*(1-gate).
// ---------------------------------------------------------------------------
__global__ __launch_bounds__(256) void proj3_kernel(
    const float* __restrict__ X,
    const float* __restrict__ Wi,
    const float* __restrict__ Wf,
    const float* __restrict__ Wg)
{
    __shared__ float As[16][128];     // transposed: As[k][m]
    __shared__ float Bs[3][16][64];   // Bs[w][k][n]

    const int tid = threadIdx.x;
    const int tx  = tid & 15;         // N direction (x4)
    const int ty  = tid >> 4;         // M direction (x8)
    const int bn  = blockIdx.x;       // 64-wide N tile
    const int bm  = blockIdx.y;       // 128-wide M tile

    const float* W[3] = {Wi, Wf, Wg};

    float acc[3][8][4];
    #pragma unroll
    for (int w = 0; w < 3; w++)
        #pragma unroll
        for (int r = 0; r < 8; r++)
            #pragma unroll
            for (int c = 0; c < 4; c++) acc[w][r][c] = 0.0f;

    for (int k0 = 0; k0 < D_; k0 += 16) {
        // load A tile (128x16): 2 float4 per thread, store transposed
        #pragma unroll
        for (int s = 0; s < 2; s++) {
            int f   = tid + s * 256;          // 0..511 (float4 index)
            int row = f >> 2;                 // 0..127
            int c4  = (f & 3) * 4;            // 0,4,8,12
            float4 v = *reinterpret_cast<const float4*>(
                &X[(size_t)(bm * 128 + row) * D_ + k0 + c4]);
            As[c4 + 0][row] = v.x; As[c4 + 1][row] = v.y;
            As[c4 + 2][row] = v.z; As[c4 + 3][row] = v.w;
        }
        // load 3 B tiles (64x16 each): 1 float4 per thread per weight
        {
            int row = tid >> 2;               // 0..63
            int c4  = (tid & 3) * 4;
            #pragma unroll
            for (int w = 0; w < 3; w++) {
                float4 v = *reinterpret_cast<const float4*>(
                    &W[w][(size_t)(bn * 64 + row) * D_ + k0 + c4]);
                Bs[w][c4 + 0][row] = v.x; Bs[w][c4 + 1][row] = v.y;
                Bs[w][c4 + 2][row] = v.z; Bs[w][c4 + 3][row] = v.w;
            }
        }
        __syncthreads();

        #pragma unroll
        for (int kk = 0; kk < 16; kk++) {
            float4 a0 = *reinterpret_cast<const float4*>(&As[kk][ty * 8]);
            float4 a1 = *reinterpret_cast<const float4*>(&As[kk][ty * 8 + 4]);
            float av[8] = {a0.x, a0.y, a0.z, a0.w, a1.x, a1.y, a1.z, a1.w};
            #pragma unroll
            for (int w = 0; w < 3; w++) {
                float4 bq = *reinterpret_cast<const float4*>(&Bs[w][kk][tx * 4]);
                float bv[4] = {bq.x, bq.y, bq.z, bq.w};
                #pragma unroll
                for (int r = 0; r < 8; r++)
                    #pragma unroll
                    for (int c = 0; c < 4; c++)
                        acc[w][r][c] = fmaf(av[r], bv[c], acc[w][r][c]);
            }
        }
        __syncthreads();
    }

    // epilogue: activations fused
    #pragma unroll
    for (int r = 0; r < 8; r++) {
        int m = bm * 128 + ty * 8 + r;
        #pragma unroll
        for (int c = 0; c < 4; c++) {
            int n = bn * 64 + tx * 4 + c;
            size_t idx = (size_t)m * D_ + n;
            float iv = acc[0][r][c];
            float fv = acc[1][r][c];
            float gate = fsigmoid(fv);
            float si   = iv * fsigmoid(iv);      // silu
            g_gate[idx] = gate;
            g_bin [idx] = si * (1.0f - gate);
            g_g   [idx] = acc[2][r][c];
        }
    }
}

// ---------------------------------------------------------------------------
// Chunked linear-recurrence scan: h_t = a_t * h_{t-1} + b_t  (per b, per d)
// ---------------------------------------------------------------------------
__global__ void scan_pass1_kernel() {
    int d = blockIdx.x * 256 + threadIdx.x;
    int c = blockIdx.y;
    int b = blockIdx.z;
    size_t base = ((size_t)b * L_ + (size_t)c * LCHUNK) * D_ + d;
    float a = 1.0f, h = 0.0f;
    #pragma unroll 4
    for (int t = 0; t < LCHUNK; t++) {
        float gt = g_gate[base + (size_t)t * D_];
        float bt = g_bin [base + (size_t)t * D_];
        h = fmaf(gt, h, bt);
        a *= gt;
    }
    size_t idx = ((size_t)b * NCHUNK + c) * D_ + d;
    g_cA[idx] = a;
    g_cH[idx] = h;
}

__global__ void scan_pass2_kernel() {
    int d = blockIdx.x * 256 + threadIdx.x;
    int b = blockIdx.y;
    float h = 0.0f;
    #pragma unroll
    for (int c = 0; c < NCHUNK; c++) {
        size_t idx = ((size_t)b * NCHUNK + c) * D_ + d;
        g_pre[idx] = h;
        h = fmaf(g_cA[idx], h, g_cH[idx]);
    }
}

__global__ void scan_pass3_kernel() {
    int d = blockIdx.x * 256 + threadIdx.x;
    int c = blockIdx.y;
    int b = blockIdx.z;
    size_t base = ((size_t)b * L_ + (size_t)c * LCHUNK) * D_ + d;
    float h = g_pre[((size_t)b * NCHUNK + c) * D_ + d];
    #pragma unroll 4
    for (int t = 0; t < LCHUNK; t++) {
        size_t p = base + (size_t)t * D_;
        float gt = g_gate[p];
        float bt = g_bin [p];
        h = fmaf(gt, h, bt);
        g_bin[p] = h;           // o overwrites b in place
    }
}

// ---------------------------------------------------------------------------
// RMSNorm(g) * weight * swish(o), one block per row, in place into g_g.
// ---------------------------------------------------------------------------
__global__ __launch_bounds__(256) void rms_gate_kernel(const float* __restrict__ gw) {
    const int m = blockIdx.x;
    const int tid = threadIdx.x;
    const float4* grow = reinterpret_cast<const float4*>(g_g  + (size_t)m * D_);
    const float4* orow = reinterpret_cast<const float4*>(g_bin + (size_t)m * D_);
    const float4* wrow = reinterpret_cast<const float4*>(gw);
    float4*       out  = reinterpret_cast<float4*>      (g_g  + (size_t)m * D_);

    float4 gv[2];
    float ss = 0.0f;
    #pragma unroll
    for (int s = 0; s < 2; s++) {
        gv[s] = grow[tid + s * 256];
        ss += gv[s].x * gv[s].x + gv[s].y * gv[s].y
            + gv[s].z * gv[s].z + gv[s].w * gv[s].w;
    }

    // block reduce (8 warps)
    __shared__ float sh[8];
    __shared__ float tot;
    int lane = tid & 31, wid = tid >> 5;
    #pragma unroll
    for (int o = 16; o > 0; o >>= 1) ss += __shfl_xor_sync(0xffffffffu, ss, o);
    if (lane == 0) sh[wid] = ss;
    __syncthreads();
    if (wid == 0) {
        float v = (lane < 8) ? sh[lane] : 0.0f;
        #pragma unroll
        for (int o = 4; o > 0; o >>= 1) v += __shfl_xor_sync(0xffffffffu, v, o);
        if (lane == 0) tot = v;
    }
    __syncthreads();

    float rms = rsqrtf(tot * (1.0f / D_) + 1e-5f);

    #pragma unroll
    for (int s = 0; s < 2; s++) {
        float4 o4 = orow[tid + s * 256];
        float4 w4 = wrow[tid + s * 256];
        float4 r;
        r.x = gv[s].x * rms * w4.x * (o4.x * fsigmoid(o4.x));
        r.y = gv[s].y * rms * w4.y * (o4.y * fsigmoid(o4.y));
        r.z = gv[s].z * rms * w4.z * (o4.z * fsigmoid(o4.z));
        r.w = gv[s].w * rms * w4.w * (o4.w * fsigmoid(o4.w));
        out[tid + s * 256] = r;
    }
}

// ---------------------------------------------------------------------------
// Kernel 4: output GEMM. Y[m,n] = sum_e out[m,e] * Wo[n,e]
// Tile: 128x128x16; 256 threads; 8x8 micro-tile.
// ---------------------------------------------------------------------------
__global__ __launch_bounds__(256) void gemm_out_kernel(
    const float* __restrict__ Wo, float* __restrict__ Y)
{
    __shared__ float As[16][128];
    __shared__ float Bs[16][128];

    const int tid = threadIdx.x;
    const int tx  = tid & 15;
    const int ty  = tid >> 4;
    const int bn  = blockIdx.x;
    const int bm  = blockIdx.y;

    float acc[8][8];
    #pragma unroll
    for (int r = 0; r < 8; r++)
        #pragma unroll
        for (int c = 0; c < 8; c++) acc[r][c] = 0.0f;

    for (int k0 = 0; k0 < D_; k0 += 16) {
        #pragma unroll
        for (int s = 0; s < 2; s++) {
            int f   = tid + s * 256;
            int row = f >> 2;
            int c4  = (f & 3) * 4;
            float4 va = *reinterpret_cast<const float4*>(
                &g_g[(size_t)(bm * 128 + row) * D_ + k0 + c4]);
            As[c4 + 0][row] = va.x; As[c4 + 1][row] = va.y;
            As[c4 + 2][row] = va.z; As[c4 + 3][row] = va.w;
            float4 vb = *reinterpret_cast<const float4*>(
                &Wo[(size_t)(bn * 128 + row) * D_ + k0 + c4]);
            Bs[c4 + 0][row] = vb.x; Bs[c4 + 1][row] = vb.y;
            Bs[c4 + 2][row] = vb.z; Bs[c4 + 3][row] = vb.w;
        }
        __syncthreads();

        #pragma unroll
        for (int kk = 0; kk < 16; kk++) {
            float4 a0 = *reinterpret_cast<const float4*>(&As[kk][ty * 8]);
            float4 a1 = *reinterpret_cast<const float4*>(&As[kk][ty * 8 + 4]);
            float4 b0 = *reinterpret_cast<const float4*>(&Bs[kk][tx * 8]);
            float4 b1 = *reinterpret_cast<const float4*>(&Bs[kk][tx * 8 + 4]);
            float av[8] = {a0.x, a0.y, a0.z, a0.w, a1.x, a1.y, a1.z, a1.w};
            float bv[8] = {b0.x, b0.y, b0.z, b0.w, b1.x, b1.y, b1.z, b1.w};
            #pragma unroll
            for (int r = 0; r < 8; r++)
                #pragma unroll
                for (int c = 0; c < 8; c++)
                    acc[r][c] = fmaf(av[r], bv[c], acc[r][c]);
        }
        __syncthreads();
    }

    #pragma unroll
    for (int r = 0; r < 8; r++) {
        int m = bm * 128 + ty * 8 + r;
        #pragma unroll
        for (int c = 0; c < 8; c++) {
            int n = bn * 128 + tx * 8 + c;
            Y[(size_t)m * D_ + n] = acc[r][c];
        }
    }
}

// ---------------------------------------------------------------------------
extern "C" void kernel_launch(void* const* d_in, const int* in_sizes, int n_in,
                              void* d_out, int out_size)
{
    const float* X  = (const float*)d_in[0];   // hidden_states [B,L,D]
    const float* Wi = (const float*)d_in[1];
    const float* Wf = (const float*)d_in[2];
    const float* Wg = (const float*)d_in[3];
    const float* gw = (const float*)d_in[4];   // g_norm_weight [D]
    const float* Wo = (const float*)d_in[5];
    float* Y = (float*)d_out;

    proj3_kernel<<<dim3(D_ / 64, M_ / 128), 256>>>(X, Wi, Wf, Wg);
    scan_pass1_kernel<<<dim3(D_ / 256, NCHUNK, B_), 256>>>();
    scan_pass2_kernel<<<dim3(D_ / 256, B_), 256>>>();
    scan_pass3_kernel<<<dim3(D_ / 256, NCHUNK, B_), 256>>>();
    rms_gate_kernel<<<M_, 256>>>(gw);
    gemm_out_kernel<<<dim3(D_ / 128, M_ / 128), 256>>>(Wo, Y);
}

// round 4
// speedup vs baseline: 2.7549x; 2.7549x over previous
#include <cuda_runtime.h>
#include <cuda_bf16.h>
#include <math.h>
#include <stdint.h>

#define B_ 4
#define L_ 4096
#define D_ 2048
#define M_ (B_*L_)            // 16384 rows
#define LCHUNK 128
#define NCHUNK (L_/LCHUNK)    // 32

// GEMM tiling: 128x128 tile, K chunk 64 bf16 (=128B row, SW128 atom)
#define KC 64
#define NKCH (D_/KC)          // 32
#define SUBBUF 16384          // 128 rows * 128B
#define STAGE_BYTES (4*SUBBUF)      // Ah, Al, Bh, Bl = 64KB
#define SMEM_TOTAL (2*STAGE_BYTES)  // 128KB double buffered

// ---------------- scratch (device globals; no allocation allowed) ----------
__device__ float g_gate[33554432];   // [M_, D_] sigmoid(f)
__device__ float g_bin [33554432];   // [M_, D_] silu(i); becomes o after scan
__device__ float g_g   [33554432];   // [M_, D_] g projection (raw)
__device__ float g_cA  [B_*NCHUNK*D_];
__device__ float g_cH  [B_*NCHUNK*D_];
__device__ float g_pre [B_*NCHUNK*D_];
__device__ __nv_bfloat16 g_Xhi[33554432], g_Xlo[33554432];
__device__ __nv_bfloat16 g_Whi[4][4194304], g_Wlo[4][4194304]; // Wi,Wf,Wg,Wo
__device__ __nv_bfloat16 g_oHi[33554432], g_oLo[33554432];     // rms-gated out

__device__ __forceinline__ float fsigmoid(float x) {
    return 1.0f / (1.0f + __expf(-x));
}

// ---------------------------- PTX helpers ----------------------------------
__device__ __forceinline__ uint32_t smem_u32(const void* p) {
    uint32_t a;
    asm("{ .reg .u64 t; cvta.to.shared.u64 t, %1; cvt.u32.u64 %0, t; }"
        : "=r"(a) : "l"(p));
    return a;
}
__device__ __forceinline__ uint32_t swz128(uint32_t off) {
    return off ^ ((off >> 3) & 0x70);
}
__device__ __forceinline__ void cpa16(uint32_t s, const void* g) {
    asm volatile("cp.async.cg.shared.global [%0], [%1], 16;" :: "r"(s), "l"(g));
}
#define CPA_COMMIT()  asm volatile("cp.async.commit_group;" ::: "memory")
#define CPA_WAIT1()   asm volatile("cp.async.wait_group 1;" ::: "memory")
#define CPA_WAIT0()   asm volatile("cp.async.wait_group 0;" ::: "memory")

__device__ __forceinline__ void ldsm4(uint32_t* r, uint32_t addr) {
    asm volatile("ldmatrix.sync.aligned.m8n8.x4.shared.b16 {%0,%1,%2,%3}, [%4];"
        : "=r"(r[0]), "=r"(r[1]), "=r"(r[2]), "=r"(r[3]) : "r"(addr));
}
__device__ __forceinline__ void mma_bf16(float* c, const uint32_t* a,
                                         uint32_t b0, uint32_t b1) {
    asm volatile(
        "mma.sync.aligned.m16n8k16.row.col.f32.bf16.bf16.f32 "
        "{%0,%1,%2,%3}, {%4,%5,%6,%7}, {%8,%9}, {%0,%1,%2,%3};"
        : "+f"(c[0]), "+f"(c[1]), "+f"(c[2]), "+f"(c[3])
        : "r"(a[0]), "r"(a[1]), "r"(a[2]), "r"(a[3]), "r"(b0), "r"(b1));
}

// ---------------------------------------------------------------------------
// fp32 -> bf16 hi/lo split.  dst: 0=X, 1..4 = Wi,Wf,Wg,Wo
// ---------------------------------------------------------------------------
__global__ __launch_bounds__(256) void split_kernel(const float* __restrict__ src,
                                                    int dst, int n) {
    __nv_bfloat16 *hi, *lo;
    if (dst == 0) { hi = g_Xhi; lo = g_Xlo; }
    else          { hi = g_Whi[dst - 1]; lo = g_Wlo[dst - 1]; }
    int i = blockIdx.x * 256 + threadIdx.x;
    if (i < n) {
        float v = src[i];
        __nv_bfloat16 h = __float2bfloat16(v);
        hi[i] = h;
        lo[i] = __float2bfloat16(v - __bfloat162float(h));
    }
}

// ---------------------------------------------------------------------------
// Split-bf16 HMMA GEMM: C[m,n] = sum_k A[m,k]*B[n,k]
// 3 MMAs per product: Ah*Bh + Ah*Bl + Al*Bh (drop Al*Bl ~ 2^-18).
// Tile 128x128, K chunk 64, 8 warps (warp tile 32x64), double-buffered cp.async.
// asel: 0 = X split, 1 = out split. bsel: 0..3 = Wi,Wf,Wg,Wo.
// dst: 0=g_gate, 1=g_bin, 2=g_g, 3=Cext.  mode: 0=silu, 1=sigmoid, 2=raw.
// ---------------------------------------------------------------------------
__global__ __launch_bounds__(256, 1) void gemm_split(int asel, int bsel,
                                                     float* Cext, int dst, int mode) {
    extern __shared__ char smem[];
    const uint32_t sb = smem_u32(smem);
    const int tid  = threadIdx.x;
    const int lane = tid & 31;
    const int wid  = tid >> 5;
    const int wm   = wid & 3;      // 4 warps over M (32 rows each)
    const int wn   = wid >> 2;     // 2 warps over N (64 cols each)
    const int bn = blockIdx.x, bm = blockIdx.y;

    const __nv_bfloat16* Ah = asel ? g_oHi : g_Xhi;
    const __nv_bfloat16* Al = asel ? g_oLo : g_Xlo;
    const __nv_bfloat16* Bh = g_Whi[bsel];
    const __nv_bfloat16* Bl = g_Wlo[bsel];
    float* C = (dst == 0) ? g_gate : (dst == 1) ? g_bin : (dst == 2) ? g_g : Cext;

    const size_t rowA = (size_t)bm * 128;
    const size_t rowB = (size_t)bn * 128;

    float acc[2][8][4];
    #pragma unroll
    for (int ma = 0; ma < 2; ma++)
        #pragma unroll
        for (int g = 0; g < 8; g++)
            #pragma unroll
            for (int q = 0; q < 4; q++) acc[ma][g][q] = 0.0f;

    // prefetch one K chunk (64 bf16) into stage (c&1): Ah,Al,Bh,Bl sub-buffers
    auto prefetch = [&](int c) {
        const int k0 = c * KC;
        const uint32_t st = sb + (uint32_t)(c & 1) * STAGE_BYTES;
        #pragma unroll
        for (int i = 0; i < 4; i++) {
            int slot = tid + i * 256;       // 0..1023
            int row  = slot >> 3;           // 0..127
            int ch   = slot & 7;            // 16B chunk within 128B row
            uint32_t so = swz128((uint32_t)row * 128 + ch * 16);
            size_t gA = (rowA + row) * D_ + k0 + ch * 8;
            size_t gB = (rowB + row) * D_ + k0 + ch * 8;
            cpa16(st + 0 * SUBBUF + so, Ah + gA);
            cpa16(st + 1 * SUBBUF + so, Al + gA);
            cpa16(st + 2 * SUBBUF + so, Bh + gB);
            cpa16(st + 3 * SUBBUF + so, Bl + gB);
        }
        CPA_COMMIT();
    };

    prefetch(0);
    prefetch(1);

    const int rowL = lane & 15;     // ldmatrix row within 16
    const int colL = lane >> 4;     // 16B chunk selector

    for (int c = 0; c < NKCH; c++) {
        if (c < NKCH - 1) { CPA_WAIT1(); } else { CPA_WAIT0(); }
        __syncthreads();

        const uint32_t st = sb + (uint32_t)(c & 1) * STAGE_BYTES;
        #pragma unroll
        for (int ks = 0; ks < 4; ks++) {
            uint32_t ah[2][4], al[2][4];
            #pragma unroll
            for (int ma = 0; ma < 2; ma++) {
                uint32_t off = swz128((uint32_t)(wm * 32 + ma * 16 + rowL) * 128
                                      + ks * 32 + colL * 16);
                ldsm4(ah[ma], st + 0 * SUBBUF + off);
                ldsm4(al[ma], st + 1 * SUBBUF + off);
            }
            #pragma unroll
            for (int g = 0; g < 4; g++) {
                uint32_t boff = swz128((uint32_t)(wn * 64 + g * 16 + rowL) * 128
                                       + ks * 32 + colL * 16);
                uint32_t bh[4], bl[4];
                ldsm4(bh, st + 2 * SUBBUF + boff);
                ldsm4(bl, st + 3 * SUBBUF + boff);
                #pragma unroll
                for (int na = 0; na < 2; na++) {
                    #pragma unroll
                    for (int ma = 0; ma < 2; ma++) {
                        float* a4 = acc[ma][g * 2 + na];
                        mma_bf16(a4, ah[ma], bh[na], bh[na + 2]);
                        mma_bf16(a4, ah[ma], bl[na], bl[na + 2]);
                        mma_bf16(a4, al[ma], bh[na], bh[na + 2]);
                    }
                }
            }
        }
        __syncthreads();
        if (c + 2 < NKCH) prefetch(c + 2);
    }

    // epilogue: direct float2 stores with fused activation
    #pragma unroll
    for (int ma = 0; ma < 2; ma++) {
        #pragma unroll
        for (int g = 0; g < 8; g++) {
            int n = (int)rowB + wn * 64 + (g >> 1) * 16 + (g & 1) * 8 + (lane & 3) * 2;
            size_t m0 = rowA + wm * 32 + ma * 16 + (lane >> 2);
            #pragma unroll
            for (int h = 0; h < 2; h++) {           // h=0: rows, h=1: rows+8
                float v0 = acc[ma][g][h * 2 + 0];
                float v1 = acc[ma][g][h * 2 + 1];
                if (mode == 0)      { v0 = v0 * fsigmoid(v0); v1 = v1 * fsigmoid(v1); }
                else if (mode == 1) { v0 = fsigmoid(v0);      v1 = fsigmoid(v1); }
                float2 pr = make_float2(v0, v1);
                *reinterpret_cast<float2*>(&C[(m0 + h * 8) * D_ + n]) = pr;
            }
        }
    }
}

// ---------------------------------------------------------------------------
// Chunked linear-recurrence scan: h_t = a_t*h_{t-1} + b_t,  b_t = si*(1-a_t)
// ---------------------------------------------------------------------------
__global__ void scan_pass1_kernel() {
    int d = blockIdx.x * 256 + threadIdx.x;
    int c = blockIdx.y;
    int b = blockIdx.z;
    size_t base = ((size_t)b * L_ + (size_t)c * LCHUNK) * D_ + d;
    float a = 1.0f, h = 0.0f;
    #pragma unroll 4
    for (int t = 0; t < LCHUNK; t++) {
        float gt = g_gate[base + (size_t)t * D_];
        float si = g_bin [base + (size_t)t * D_];
        h = fmaf(gt, h, si * (1.0f - gt));
        a *= gt;
    }
    size_t idx = ((size_t)b * NCHUNK + c) * D_ + d;
    g_cA[idx] = a;
    g_cH[idx] = h;
}

__global__ void scan_pass2_kernel() {
    int d = blockIdx.x * 256 + threadIdx.x;
    int b = blockIdx.y;
    float h = 0.0f;
    #pragma unroll
    for (int c = 0; c < NCHUNK; c++) {
        size_t idx = ((size_t)b * NCHUNK + c) * D_ + d;
        g_pre[idx] = h;
        h = fmaf(g_cA[idx], h, g_cH[idx]);
    }
}

__global__ void scan_pass3_kernel() {
    int d = blockIdx.x * 256 + threadIdx.x;
    int c = blockIdx.y;
    int b = blockIdx.z;
    size_t base = ((size_t)b * L_ + (size_t)c * LCHUNK) * D_ + d;
    float h = g_pre[((size_t)b * NCHUNK + c) * D_ + d];
    #pragma unroll 4
    for (int t = 0; t < LCHUNK; t++) {
        size_t p = base + (size_t)t * D_;
        float gt = g_gate[p];
        float si = g_bin [p];
        h = fmaf(gt, h, si * (1.0f - gt));
        g_bin[p] = h;           // o overwrites silu(i) in place
    }
}

// ---------------------------------------------------------------------------
// RMSNorm(g)*weight*swish(o); writes bf16 hi/lo split for the output GEMM.
// ---------------------------------------------------------------------------
__global__ __launch_bounds__(256) void rms_gate_kernel(const float* __restrict__ gw) {
    const int m = blockIdx.x;
    const int tid = threadIdx.x;
    const float4* grow = reinterpret_cast<const float4*>(g_g  + (size_t)m * D_);
    const float4* orow = reinterpret_cast<const float4*>(g_bin + (size_t)m * D_);
    const float4* wrow = reinterpret_cast<const float4*>(gw);

    float4 gv[2];
    float ss = 0.0f;
    #pragma unroll
    for (int s = 0; s < 2; s++) {
        gv[s] = grow[tid + s * 256];
        ss += gv[s].x * gv[s].x + gv[s].y * gv[s].y
            + gv[s].z * gv[s].z + gv[s].w * gv[s].w;
    }

    __shared__ float sh[8];
    __shared__ float tot;
    int lane = tid & 31, wid = tid >> 5;
    #pragma unroll
    for (int o = 16; o > 0; o >>= 1) ss += __shfl_xor_sync(0xffffffffu, ss, o);
    if (lane == 0) sh[wid] = ss;
    __syncthreads();
    if (wid == 0) {
        float v = (lane < 8) ? sh[lane] : 0.0f;
        #pragma unroll
        for (int o = 4; o > 0; o >>= 1) v += __shfl_xor_sync(0xffffffffu, v, o);
        if (lane == 0) tot = v;
    }
    __syncthreads();

    float rms = rsqrtf(tot * (1.0f / D_) + 1e-5f);

    #pragma unroll
    for (int s = 0; s < 2; s++) {
        float4 o4 = orow[tid + s * 256];
        float4 w4 = wrow[tid + s * 256];
        float r[4];
        r[0] = gv[s].x * rms * w4.x * (o4.x * fsigmoid(o4.x));
        r[1] = gv[s].y * rms * w4.y * (o4.y * fsigmoid(o4.y));
        r[2] = gv[s].z * rms * w4.z * (o4.z * fsigmoid(o4.z));
        r[3] = gv[s].w * rms * w4.w * (o4.w * fsigmoid(o4.w));
        size_t base = (size_t)m * D_ + (tid + s * 256) * 4;
        #pragma unroll
        for (int q = 0; q < 4; q++) {
            __nv_bfloat16 h = __float2bfloat16(r[q]);
            g_oHi[base + q] = h;
            g_oLo[base + q] = __float2bfloat16(r[q] - __bfloat162float(h));
        }
    }
}

// ---------------------------------------------------------------------------
extern "C" void kernel_launch(void* const* d_in, const int* in_sizes, int n_in,
                              void* d_out, int out_size)
{
    const float* X  = (const float*)d_in[0];
    const float* Wi = (const float*)d_in[1];
    const float* Wf = (const float*)d_in[2];
    const float* Wg = (const float*)d_in[3];
    const float* gw = (const float*)d_in[4];
    const float* Wo = (const float*)d_in[5];
    float* Y = (float*)d_out;

    static int smem_set = 0;
    if (!smem_set) {
        cudaFuncSetAttribute(gemm_split, cudaFuncAttributeMaxDynamicSharedMemorySize,
                             SMEM_TOTAL);
        smem_set = 1;
    }

    // fp32 -> bf16 hi/lo splits
    split_kernel<<<(M_ * D_ + 255) / 256, 256>>>(X,  0, M_ * D_);
    split_kernel<<<(D_ * D_ + 255) / 256, 256>>>(Wi, 1, D_ * D_);
    split_kernel<<<(D_ * D_ + 255) / 256, 256>>>(Wf, 2, D_ * D_);
    split_kernel<<<(D_ * D_ + 255) / 256, 256>>>(Wg, 3, D_ * D_);
    split_kernel<<<(D_ * D_ + 255) / 256, 256>>>(Wo, 4, D_ * D_);

    dim3 gg(D_ / 128, M_ / 128);
    // f -> sigmoid -> g_gate ; i -> silu -> g_bin ; g -> raw -> g_g
    gemm_split<<<gg, 256, SMEM_TOTAL>>>(0, 1, Y, 0, 1);
    gemm_split<<<gg, 256, SMEM_TOTAL>>>(0, 0, Y, 1, 0);
    gemm_split<<<gg, 256, SMEM_TOTAL>>>(0, 2, Y, 2, 2);

    scan_pass1_kernel<<<dim3(D_ / 256, NCHUNK, B_), 256>>>();
    scan_pass2_kernel<<<dim3(D_ / 256, B_), 256>>>();
    scan_pass3_kernel<<<dim3(D_ / 256, NCHUNK, B_), 256>>>();

    rms_gate_kernel<<<M_, 256>>>(gw);

    // out @ Wo^T -> Y
    gemm_split<<<gg, 256, SMEM_TOTAL>>>(1, 3, Y, 3, 2);
}

// round 5
// speedup vs baseline: 2.9029x; 1.0537x over previous
#include <cuda_runtime.h>
#include <cuda_bf16.h>
#include <math.h>
#include <stdint.h>

#define B_ 4
#define L_ 4096
#define D_ 2048
#define M_ (B_*L_)            // 16384 rows
#define LCHUNK 128
#define NCHUNK (L_/LCHUNK)    // 32

// GEMM tiling: 128x128 tile, K chunk 32 bf16 (=64B row, SW64 swizzle)
#define KC 32
#define NKCH (D_/KC)          // 64
#define SUB 8192              // 128 rows * 64B
#define STAGE (4*SUB)         // Ah, Al, Bh, Bl = 32KB
#define SMEM_TOTAL (2*STAGE)  // 64KB double buffered -> 2 CTAs/SM

// ---------------- scratch (device globals; no allocation allowed) ----------
__device__ float g_gate[33554432];   // [M_, D_] sigmoid(f)
__device__ float g_bin [33554432];   // [M_, D_] silu(i); becomes o after scan
__device__ float g_g   [33554432];   // [M_, D_] g projection (raw)
__device__ float g_cA  [B_*NCHUNK*D_];
__device__ float g_cH  [B_*NCHUNK*D_];
__device__ float g_pre [B_*NCHUNK*D_];
__device__ __nv_bfloat16 g_Xhi[33554432], g_Xlo[33554432];
__device__ __nv_bfloat16 g_Whi[4][4194304], g_Wlo[4][4194304]; // Wi,Wf,Wg,Wo
__device__ __nv_bfloat16 g_oHi[33554432], g_oLo[33554432];     // rms-gated out

__device__ __forceinline__ float fsigmoid(float x) {
    return 1.0f / (1.0f + __expf(-x));
}

// ---------------------------- PTX helpers ----------------------------------
__device__ __forceinline__ uint32_t smem_u32(const void* p) {
    uint32_t a;
    asm("{ .reg .u64 t; cvta.to.shared.u64 t, %1; cvt.u32.u64 %0, t; }"
        : "=r"(a) : "l"(p));
    return a;
}
__device__ __forceinline__ uint32_t swz64(uint32_t off) {
    return off ^ ((off >> 3) & 0x30);
}
__device__ __forceinline__ void cpa16(uint32_t s, const void* g) {
    asm volatile("cp.async.cg.shared.global [%0], [%1], 16;" :: "r"(s), "l"(g));
}
#define CPA_COMMIT()  asm volatile("cp.async.commit_group;" ::: "memory")
#define CPA_WAIT1()   asm volatile("cp.async.wait_group 1;" ::: "memory")
#define CPA_WAIT0()   asm volatile("cp.async.wait_group 0;" ::: "memory")

__device__ __forceinline__ void ldsm4(uint32_t* r, uint32_t addr) {
    asm volatile("ldmatrix.sync.aligned.m8n8.x4.shared.b16 {%0,%1,%2,%3}, [%4];"
        : "=r"(r[0]), "=r"(r[1]), "=r"(r[2]), "=r"(r[3]) : "r"(addr));
}
__device__ __forceinline__ void mma_bf16(float* c, const uint32_t* a,
                                         uint32_t b0, uint32_t b1) {
    asm volatile(
        "mma.sync.aligned.m16n8k16.row.col.f32.bf16.bf16.f32 "
        "{%0,%1,%2,%3}, {%4,%5,%6,%7}, {%8,%9}, {%0,%1,%2,%3};"
        : "+f"(c[0]), "+f"(c[1]), "+f"(c[2]), "+f"(c[3])
        : "r"(a[0]), "r"(a[1]), "r"(a[2]), "r"(a[3]), "r"(b0), "r"(b1));
}

// ---------------------------------------------------------------------------
// fp32 -> bf16 hi/lo splits (vectorized: float4 in, 4xbf16 = 8B out per array)
// ---------------------------------------------------------------------------
__device__ __forceinline__ void split4(const float4 v, uint2* hi4, uint2* lo4) {
    __nv_bfloat16 h[4], l[4];
    float f[4] = {v.x, v.y, v.z, v.w};
    #pragma unroll
    for (int q = 0; q < 4; q++) {
        h[q] = __float2bfloat16(f[q]);
        l[q] = __float2bfloat16(f[q] - __bfloat162float(h[q]));
    }
    *hi4 = *reinterpret_cast<uint2*>(h);
    *lo4 = *reinterpret_cast<uint2*>(l);
}

__global__ __launch_bounds__(256) void splitX_kernel(const float* __restrict__ src) {
    int i = blockIdx.x * 256 + threadIdx.x;          // float4 index
    float4 v = reinterpret_cast<const float4*>(src)[i];
    uint2 h, l;
    split4(v, &h, &l);
    reinterpret_cast<uint2*>(g_Xhi)[i] = h;
    reinterpret_cast<uint2*>(g_Xlo)[i] = l;
}

__global__ __launch_bounds__(256) void splitW_kernel(
    const float* __restrict__ w0, const float* __restrict__ w1,
    const float* __restrict__ w2, const float* __restrict__ w3) {
    const float* src = (blockIdx.y == 0) ? w0 : (blockIdx.y == 1) ? w1
                     : (blockIdx.y == 2) ? w2 : w3;
    int i = blockIdx.x * 256 + threadIdx.x;          // float4 index
    float4 v = reinterpret_cast<const float4*>(src)[i];
    uint2 h, l;
    split4(v, &h, &l);
    reinterpret_cast<uint2*>(g_Whi[blockIdx.y])[i] = h;
    reinterpret_cast<uint2*>(g_Wlo[blockIdx.y])[i] = l;
}

// ---------------------------------------------------------------------------
// Split-bf16 HMMA GEMM: C[m,n] = sum_k A[m,k]*B[n,k]
// 3 MMAs per product: Ah*Bh + Ah*Bl + Al*Bh.
// Tile 128x128, K chunk 32, 8 warps (warp tile 32x64), 2 CTAs/SM.
// fused=1: projection (blockIdx.y = weight 0..2 -> Wi/Wf/Wg with silu/sigmoid/raw)
// fused=0: output GEMM (Wo, raw) into Cext.
// ---------------------------------------------------------------------------
__global__ __launch_bounds__(256, 2) void gemm_split(int fused, float* Cext) {
    extern __shared__ char smem[];
    const uint32_t sb = smem_u32(smem);
    const int tid  = threadIdx.x;
    const int lane = tid & 31;
    const int wid  = tid >> 5;
    const int wm   = wid & 3;      // 4 warps over M (32 rows each)
    const int wn   = wid >> 2;     // 2 warps over N (64 cols each)
    const int bn = blockIdx.x;
    const int w  = fused ? blockIdx.y : 3;
    const int bm = blockIdx.z;
    const int mode = fused ? ((w == 0) ? 0 : (w == 1) ? 1 : 2) : 2;

    const __nv_bfloat16* Ah = fused ? g_Xhi : g_oHi;
    const __nv_bfloat16* Al = fused ? g_Xlo : g_oLo;
    const __nv_bfloat16* Bh = g_Whi[w];
    const __nv_bfloat16* Bl = g_Wlo[w];
    float* C = fused ? ((w == 0) ? g_bin : (w == 1) ? g_gate : g_g) : Cext;

    const size_t rowA = (size_t)bm * 128;
    const size_t rowB = (size_t)bn * 128;

    float acc[2][8][4];
    #pragma unroll
    for (int ma = 0; ma < 2; ma++)
        #pragma unroll
        for (int g = 0; g < 8; g++)
            #pragma unroll
            for (int q = 0; q < 4; q++) acc[ma][g][q] = 0.0f;

    // prefetch one K chunk (32 bf16 = 64B/row) into stage (c&1)
    auto prefetch = [&](int c) {
        const int k0 = c * KC;
        const uint32_t st = sb + (uint32_t)(c & 1) * STAGE;
        #pragma unroll
        for (int i = 0; i < 2; i++) {
            int slot = tid + i * 256;       // 0..511
            int row  = slot >> 2;           // 0..127
            int ch   = slot & 3;            // 16B chunk within 64B row
            uint32_t so = swz64((uint32_t)row * 64 + ch * 16);
            size_t gA = (rowA + row) * D_ + k0 + ch * 8;
            size_t gB = (rowB + row) * D_ + k0 + ch * 8;
            cpa16(st + 0 * SUB + so, Ah + gA);
            cpa16(st + 1 * SUB + so, Al + gA);
            cpa16(st + 2 * SUB + so, Bh + gB);
            cpa16(st + 3 * SUB + so, Bl + gB);
        }
        CPA_COMMIT();
    };

    prefetch(0);
    prefetch(1);

    const int rowL = lane & 15;     // ldmatrix row within 16
    const int colL = lane >> 4;     // 16B chunk selector

    for (int c = 0; c < NKCH; c++) {
        if (c < NKCH - 1) { CPA_WAIT1(); } else { CPA_WAIT0(); }
        __syncthreads();

        const uint32_t st = sb + (uint32_t)(c & 1) * STAGE;
        #pragma unroll
        for (int ks = 0; ks < 2; ks++) {
            uint32_t ah[2][4], al[2][4];
            #pragma unroll
            for (int ma = 0; ma < 2; ma++) {
                uint32_t off = swz64((uint32_t)(wm * 32 + ma * 16 + rowL) * 64
                                     + ks * 32 + colL * 16);
                ldsm4(ah[ma], st + 0 * SUB + off);
                ldsm4(al[ma], st + 1 * SUB + off);
            }
            #pragma unroll
            for (int g = 0; g < 4; g++) {
                uint32_t boff = swz64((uint32_t)(wn * 64 + g * 16 + rowL) * 64
                                      + ks * 32 + colL * 16);
                uint32_t bh[4], bl[4];
                ldsm4(bh, st + 2 * SUB + boff);
                ldsm4(bl, st + 3 * SUB + boff);
                #pragma unroll
                for (int na = 0; na < 2; na++) {
                    #pragma unroll
                    for (int ma = 0; ma < 2; ma++) {
                        float* a4 = acc[ma][g * 2 + na];
                        mma_bf16(a4, ah[ma], bh[na], bh[na + 2]);
                        mma_bf16(a4, ah[ma], bl[na], bl[na + 2]);
                        mma_bf16(a4, al[ma], bh[na], bh[na + 2]);
                    }
                }
            }
        }
        __syncthreads();
        if (c + 2 < NKCH) prefetch(c + 2);
    }

    // epilogue: direct float2 stores with fused activation
    #pragma unroll
    for (int ma = 0; ma < 2; ma++) {
        #pragma unroll
        for (int g = 0; g < 8; g++) {
            int n = (int)rowB + wn * 64 + (g >> 1) * 16 + (g & 1) * 8 + (lane & 3) * 2;
            size_t m0 = rowA + wm * 32 + ma * 16 + (lane >> 2);
            #pragma unroll
            for (int h = 0; h < 2; h++) {           // h=0: rows, h=1: rows+8
                float v0 = acc[ma][g][h * 2 + 0];
                float v1 = acc[ma][g][h * 2 + 1];
                if (mode == 0)      { v0 = v0 * fsigmoid(v0); v1 = v1 * fsigmoid(v1); }
                else if (mode == 1) { v0 = fsigmoid(v0);      v1 = fsigmoid(v1); }
                float2 pr = make_float2(v0, v1);
                *reinterpret_cast<float2*>(&C[(m0 + h * 8) * D_ + n]) = pr;
            }
        }
    }
}

// ---------------------------------------------------------------------------
// Chunked linear-recurrence scan: h_t = a_t*h_{t-1} + b_t,  b_t = si*(1-a_t)
// ---------------------------------------------------------------------------
__global__ void scan_pass1_kernel() {
    int d = blockIdx.x * 256 + threadIdx.x;
    int c = blockIdx.y;
    int b = blockIdx.z;
    size_t base = ((size_t)b * L_ + (size_t)c * LCHUNK) * D_ + d;
    float a = 1.0f, h = 0.0f;
    #pragma unroll 4
    for (int t = 0; t < LCHUNK; t++) {
        float gt = g_gate[base + (size_t)t * D_];
        float si = g_bin [base + (size_t)t * D_];
        h = fmaf(gt, h, si * (1.0f - gt));
        a *= gt;
    }
    size_t idx = ((size_t)b * NCHUNK + c) * D_ + d;
    g_cA[idx] = a;
    g_cH[idx] = h;
}

__global__ void scan_pass2_kernel() {
    int d = blockIdx.x * 256 + threadIdx.x;
    int b = blockIdx.y;
    float h = 0.0f;
    #pragma unroll
    for (int c = 0; c < NCHUNK; c++) {
        size_t idx = ((size_t)b * NCHUNK + c) * D_ + d;
        g_pre[idx] = h;
        h = fmaf(g_cA[idx], h, g_cH[idx]);
    }
}

__global__ void scan_pass3_kernel() {
    int d = blockIdx.x * 256 + threadIdx.x;
    int c = blockIdx.y;
    int b = blockIdx.z;
    size_t base = ((size_t)b * L_ + (size_t)c * LCHUNK) * D_ + d;
    float h = g_pre[((size_t)b * NCHUNK + c) * D_ + d];
    #pragma unroll 4
    for (int t = 0; t < LCHUNK; t++) {
        size_t p = base + (size_t)t * D_;
        float gt = g_gate[p];
        float si = g_bin [p];
        h = fmaf(gt, h, si * (1.0f - gt));
        g_bin[p] = h;           // o overwrites silu(i) in place
    }
}

// ---------------------------------------------------------------------------
// RMSNorm(g)*weight*swish(o); writes bf16 hi/lo split for the output GEMM.
// ---------------------------------------------------------------------------
__global__ __launch_bounds__(256) void rms_gate_kernel(const float* __restrict__ gw) {
    const int m = blockIdx.x;
    const int tid = threadIdx.x;
    const float4* grow = reinterpret_cast<const float4*>(g_g  + (size_t)m * D_);
    const float4* orow = reinterpret_cast<const float4*>(g_bin + (size_t)m * D_);
    const float4* wrow = reinterpret_cast<const float4*>(gw);

    float4 gv[2];
    float ss = 0.0f;
    #pragma unroll
    for (int s = 0; s < 2; s++) {
        gv[s] = grow[tid + s * 256];
        ss += gv[s].x * gv[s].x + gv[s].y * gv[s].y
            + gv[s].z * gv[s].z + gv[s].w * gv[s].w;
    }

    __shared__ float sh[8];
    __shared__ float tot;
    int lane = tid & 31, wid = tid >> 5;
    #pragma unroll
    for (int o = 16; o > 0; o >>= 1) ss += __shfl_xor_sync(0xffffffffu, ss, o);
    if (lane == 0) sh[wid] = ss;
    __syncthreads();
    if (wid == 0) {
        float v = (lane < 8) ? sh[lane] : 0.0f;
        #pragma unroll
        for (int o = 4; o > 0; o >>= 1) v += __shfl_xor_sync(0xffffffffu, v, o);
        if (lane == 0) tot = v;
    }
    __syncthreads();

    float rms = rsqrtf(tot * (1.0f / D_) + 1e-5f);

    #pragma unroll
    for (int s = 0; s < 2; s++) {
        float4 o4 = orow[tid + s * 256];
        float4 w4 = wrow[tid + s * 256];
        float4 r;
        r.x = gv[s].x * rms * w4.x * (o4.x * fsigmoid(o4.x));
        r.y = gv[s].y * rms * w4.y * (o4.y * fsigmoid(o4.y));
        r.z = gv[s].z * rms * w4.z * (o4.z * fsigmoid(o4.z));
        r.w = gv[s].w * rms * w4.w * (o4.w * fsigmoid(o4.w));
        uint2 h, l;
        split4(r, &h, &l);
        size_t b4 = (size_t)m * (D_ / 4) + tid + s * 256;
        reinterpret_cast<uint2*>(g_oHi)[b4] = h;
        reinterpret_cast<uint2*>(g_oLo)[b4] = l;
    }
}

// ---------------------------------------------------------------------------
extern "C" void kernel_launch(void* const* d_in, const int* in_sizes, int n_in,
                              void* d_out, int out_size)
{
    const float* X  = (const float*)d_in[0];
    const float* Wi = (const float*)d_in[1];
    const float* Wf = (const float*)d_in[2];
    const float* Wg = (const float*)d_in[3];
    const float* gw = (const float*)d_in[4];
    const float* Wo = (const float*)d_in[5];
    float* Y = (float*)d_out;

    static int smem_set = 0;
    if (!smem_set) {
        cudaFuncSetAttribute(gemm_split, cudaFuncAttributeMaxDynamicSharedMemorySize,
                             SMEM_TOTAL);
        smem_set = 1;
    }

    // fp32 -> bf16 hi/lo splits (vectorized)
    splitX_kernel<<<(M_ * D_ / 4) / 256, 256>>>(X);
    splitW_kernel<<<dim3((D_ * D_ / 4) / 256, 4), 256>>>(Wi, Wf, Wg, Wo);

    // fused i/f/g projections: grid y = weight, z = M tile (L2 A-tile reuse)
    gemm_split<<<dim3(D_ / 128, 3, M_ / 128), 256, SMEM_TOTAL>>>(1, Y);

    scan_pass1_kernel<<<dim3(D_ / 256, NCHUNK, B_), 256>>>();
    scan_pass2_kernel<<<dim3(D_ / 256, B_), 256>>>();
    scan_pass3_kernel<<<dim3(D_ / 256, NCHUNK, B_), 256>>>();

    rms_gate_kernel<<<M_, 256>>>(gw);

    // out @ Wo^T -> Y
    gemm_split<<<dim3(D_ / 128, 1, M_ / 128), 256, SMEM_TOTAL>>>(0, Y);
}